// round 13
// baseline (speedup 1.0000x reference)
#include <cuda_runtime.h>

#define W 8192

static __device__ __align__(16) float g_bufA[8 * 32 * W];
static __device__ __align__(16) float g_bufB[8 * 32 * W];

// ---- packed f32x2 helpers (sm_103a FFMA2 path) ----------------------------
__device__ __forceinline__ unsigned long long ffma2(
    unsigned long long a, unsigned long long b, unsigned long long c)
{
    unsigned long long d;
    asm("fma.rn.f32x2 %0, %1, %2, %3;" : "=l"(d) : "l"(a), "l"(b), "l"(c));
    return d;
}
__device__ __forceinline__ unsigned long long pack2(float lo, float hi)
{
    unsigned long long r;
    asm("mov.b64 %0, {%1, %2};" : "=l"(r) : "f"(lo), "f"(hi));
    return r;
}
__device__ __forceinline__ float2 unpack2(unsigned long long v)
{
    float2 r;
    asm("mov.b64 {%0, %1}, %2;" : "=f"(r.x), "=f"(r.y) : "l"(v));
    return r;
}
__device__ __forceinline__ float tanh_approx(float x)
{
    float y;
    asm("tanh.approx.f32 %0, %1;" : "=f"(y) : "f"(x));
    return y;
}

// ---------------------------------------------------------------------------
// Start conv: bufA[b,c,ti] = sum_k start_w[c,k] * x_input[b,k,8192+ti]
// ---------------------------------------------------------------------------
__global__ __launch_bounds__(128) void start_kernel(
    const float* __restrict__ x_input, const float* __restrict__ start_w)
{
    __shared__ __align__(16) float wsm[32 * 256];  // [c][k]
    const int b = blockIdx.y;
    for (int i = threadIdx.x; i < 32 * 256; i += 128) wsm[i] = start_w[i];
    __syncthreads();

    const int ti = (blockIdx.x * 128 + threadIdx.x) * 2;
    const float* xb = x_input + (size_t)b * 256 * 16384 + 8192 + ti;

    float2 acc[32];
#pragma unroll
    for (int c = 0; c < 32; c++) acc[c] = make_float2(0.f, 0.f);

    const float4* wv = (const float4*)wsm;
#pragma unroll 4
    for (int k4 = 0; k4 < 64; k4++) {
        float2 x0 = *(const float2*)(xb + (size_t)(k4 * 4 + 0) * 16384);
        float2 x1 = *(const float2*)(xb + (size_t)(k4 * 4 + 1) * 16384);
        float2 x2 = *(const float2*)(xb + (size_t)(k4 * 4 + 2) * 16384);
        float2 x3 = *(const float2*)(xb + (size_t)(k4 * 4 + 3) * 16384);
#pragma unroll
        for (int c = 0; c < 32; c++) {
            float4 w = wv[c * 64 + k4];
            acc[c].x = fmaf(w.x, x0.x, acc[c].x);
            acc[c].y = fmaf(w.x, x0.y, acc[c].y);
            acc[c].x = fmaf(w.y, x1.x, acc[c].x);
            acc[c].y = fmaf(w.y, x1.y, acc[c].y);
            acc[c].x = fmaf(w.z, x2.x, acc[c].x);
            acc[c].y = fmaf(w.z, x2.y, acc[c].y);
            acc[c].x = fmaf(w.w, x3.x, acc[c].x);
            acc[c].y = fmaf(w.w, x3.y, acc[c].y);
        }
    }
#pragma unroll
    for (int c = 0; c < 32; c++)
        *(float2*)(&g_bufA[((size_t)b * 32 + c) * W + ti]) = acc[c];
}

// ---------------------------------------------------------------------------
// WaveNet layer: 2 positions/thread (strided by 64) x half-channel split.
// Block = 128 threads = 2 halves x 64 thread-positions = 128 positions.
// Weights via uniform __ldg (L1-resident). LDS:FFMA2 = 1:4 via weight reuse
// across the position pair. smem: exch 32KB + zsh 16KB = 48KB static.
// ---------------------------------------------------------------------------
__global__ __launch_bounds__(128, 4) void layer_kernel(
    const float* __restrict__ filt, const float* __restrict__ gate,
    const float* __restrict__ resid, int d, int tstart, int dir, int last)
{
    __shared__ __align__(16) float exch[32 * 2 * 128];  // [c][pa|pg][pos]
    __shared__ __align__(16) float zsh[32 * 128];       // [c][pos]

    const float* xin  = dir ? g_bufB : g_bufA;
    float*       xout = dir ? g_bufA : g_bufB;

    const int tp = threadIdx.x & 63;
    const int h  = threadIdx.x >> 6;
    const int hc = h << 4;

    const int base = tstart + blockIdx.x * 128;
    const int ti0 = base + tp;
    const int ti1 = ti0 + 64;
    const bool v0 = (ti0 < W), v1 = (ti1 < W);
    const int t0 = v0 ? ti0 : (W - 1);
    const int t1 = v1 ? ti1 : (W - 1);

    const float* xb = xin + (size_t)blockIdx.y * 32 * W;

    // (prev,cur) packed for this half's 16 in-channels, both positions
    unsigned long long cp0[16], cp1[16];
#pragma unroll
    for (int r = 0; r < 16; r++) {
        const float* xr = xb + (hc + r) * W;
        cp0[r] = pack2(xr[t0 - d], xr[t0]);
        cp1[r] = pack2(xr[t1 - d], xr[t1]);
    }

    // ---- phase A: partial gated sums for the OTHER half's out channels ----
    const int oc0 = 16 - hc;
#pragma unroll 4
    for (int cl = 0; cl < 16; cl++) {
        const int c = oc0 + cl;
        const ulonglong2* fw = (const ulonglong2*)(filt + c * 64 + hc * 2);
        const ulonglong2* gw = (const ulonglong2*)(gate + c * 64 + hc * 2);
        unsigned long long fa0 = 0, fb0 = 0, fa1 = 0, fb1 = 0;
        unsigned long long ga0 = 0, gb0 = 0, ga1 = 0, gb1 = 0;
#pragma unroll
        for (int j = 0; j < 8; j++) {
            ulonglong2 wf = __ldg(fw + j);
            ulonglong2 wg = __ldg(gw + j);
            fa0 = ffma2(wf.x, cp0[2 * j],     fa0);
            fb0 = ffma2(wf.y, cp0[2 * j + 1], fb0);
            fa1 = ffma2(wf.x, cp1[2 * j],     fa1);
            fb1 = ffma2(wf.y, cp1[2 * j + 1], fb1);
            ga0 = ffma2(wg.x, cp0[2 * j],     ga0);
            gb0 = ffma2(wg.y, cp0[2 * j + 1], gb0);
            ga1 = ffma2(wg.x, cp1[2 * j],     ga1);
            gb1 = ffma2(wg.y, cp1[2 * j + 1], gb1);
        }
        float2 u, v;
        u = unpack2(fa0); v = unpack2(fb0);
        exch[(c * 2 + 0) * 128 + tp]      = (u.x + u.y) + (v.x + v.y);
        u = unpack2(fa1); v = unpack2(fb1);
        exch[(c * 2 + 0) * 128 + tp + 64] = (u.x + u.y) + (v.x + v.y);
        u = unpack2(ga0); v = unpack2(gb0);
        exch[(c * 2 + 1) * 128 + tp]      = (u.x + u.y) + (v.x + v.y);
        u = unpack2(ga1); v = unpack2(gb1);
        exch[(c * 2 + 1) * 128 + tp + 64] = (u.x + u.y) + (v.x + v.y);
    }
    __syncthreads();

    // ---- phase C: OWN out channels: partial + exch, activate, z -> zsh ----
#pragma unroll 4
    for (int cl = 0; cl < 16; cl++) {
        const int c = hc + cl;
        const ulonglong2* fw = (const ulonglong2*)(filt + c * 64 + hc * 2);
        const ulonglong2* gw = (const ulonglong2*)(gate + c * 64 + hc * 2);
        unsigned long long fa0 = 0, fb0 = 0, fa1 = 0, fb1 = 0;
        unsigned long long ga0 = 0, gb0 = 0, ga1 = 0, gb1 = 0;
#pragma unroll
        for (int j = 0; j < 8; j++) {
            ulonglong2 wf = __ldg(fw + j);
            ulonglong2 wg = __ldg(gw + j);
            fa0 = ffma2(wf.x, cp0[2 * j],     fa0);
            fb0 = ffma2(wf.y, cp0[2 * j + 1], fb0);
            fa1 = ffma2(wf.x, cp1[2 * j],     fa1);
            fb1 = ffma2(wf.y, cp1[2 * j + 1], fb1);
            ga0 = ffma2(wg.x, cp0[2 * j],     ga0);
            gb0 = ffma2(wg.y, cp0[2 * j + 1], gb0);
            ga1 = ffma2(wg.x, cp1[2 * j],     ga1);
            gb1 = ffma2(wg.y, cp1[2 * j + 1], gb1);
        }
        float2 u, v;
        u = unpack2(fa0); v = unpack2(fb0);
        float pa0 = (u.x + u.y) + (v.x + v.y) + exch[(c * 2 + 0) * 128 + tp];
        u = unpack2(fa1); v = unpack2(fb1);
        float pa1 = (u.x + u.y) + (v.x + v.y) + exch[(c * 2 + 0) * 128 + tp + 64];
        u = unpack2(ga0); v = unpack2(gb0);
        float pg0 = (u.x + u.y) + (v.x + v.y) + exch[(c * 2 + 1) * 128 + tp];
        u = unpack2(ga1); v = unpack2(gb1);
        float pg1 = (u.x + u.y) + (v.x + v.y) + exch[(c * 2 + 1) * 128 + tp + 64];

        // tanh(a)*sigmoid(g), sigmoid via tanh: s(g)=0.5*(1+tanh(g/2))
        float z0 = tanh_approx(pa0) * fmaf(0.5f, tanh_approx(0.5f * pg0), 0.5f);
        float z1 = tanh_approx(pa1) * fmaf(0.5f, tanh_approx(0.5f * pg1), 0.5f);

        if (last) {
            float* ob = xout + (size_t)blockIdx.y * 32 * W + c * W;
            if (v0) ob[ti0] = z0;
            if (v1) ob[ti1] = z1;
        } else {
            zsh[c * 128 + tp]      = z0;
            zsh[c * 128 + tp + 64] = z1;
        }
    }
    if (last) return;       // uniform across block
    __syncthreads();

    // ---- phase E: residual conv for OWN 16 out channels, both positions ----
    float acc0[16], acc1[16];
#pragma unroll
    for (int cl = 0; cl < 16; cl++) {
        acc0[cl] = unpack2(cp0[cl]).y;   // + cur (residual input)
        acc1[cl] = unpack2(cp1[cl]).y;
    }
#pragma unroll
    for (int k = 0; k < 4; k++) {        // z channels in chunks of 8
        float zf0[8], zf1[8];
#pragma unroll
        for (int r = 0; r < 8; r++) {
            zf0[r] = zsh[(8 * k + r) * 128 + tp];
            zf1[r] = zsh[(8 * k + r) * 128 + tp + 64];
        }
#pragma unroll
        for (int cl = 0; cl < 16; cl++) {
            const float4* rw = (const float4*)(resid + (hc + cl) * 32 + 8 * k);
            float4 w0 = __ldg(rw);
            float4 w1 = __ldg(rw + 1);
            acc0[cl] = fmaf(w0.x, zf0[0], acc0[cl]);
            acc1[cl] = fmaf(w0.x, zf1[0], acc1[cl]);
            acc0[cl] = fmaf(w0.y, zf0[1], acc0[cl]);
            acc1[cl] = fmaf(w0.y, zf1[1], acc1[cl]);
            acc0[cl] = fmaf(w0.z, zf0[2], acc0[cl]);
            acc1[cl] = fmaf(w0.z, zf1[2], acc1[cl]);
            acc0[cl] = fmaf(w0.w, zf0[3], acc0[cl]);
            acc1[cl] = fmaf(w0.w, zf1[3], acc1[cl]);
            acc0[cl] = fmaf(w1.x, zf0[4], acc0[cl]);
            acc1[cl] = fmaf(w1.x, zf1[4], acc1[cl]);
            acc0[cl] = fmaf(w1.y, zf0[5], acc0[cl]);
            acc1[cl] = fmaf(w1.y, zf1[5], acc1[cl]);
            acc0[cl] = fmaf(w1.z, zf0[6], acc0[cl]);
            acc1[cl] = fmaf(w1.z, zf1[6], acc1[cl]);
            acc0[cl] = fmaf(w1.w, zf0[7], acc0[cl]);
            acc1[cl] = fmaf(w1.w, zf1[7], acc1[cl]);
        }
    }

    float* ob = xout + (size_t)blockIdx.y * 32 * W;
#pragma unroll
    for (int cl = 0; cl < 16; cl++) {
        const int c = hc + cl;
        if (v0) ob[c * W + ti0] = acc0[cl];
        if (v1) ob[c * W + ti1] = acc1[cl];
    }
}

// ---------------------------------------------------------------------------
// Fused head: out = e2 @ relu(e1 @ relu(skip39 @ z) + b1) + b2
// (verified R11 version, unchanged)
// ---------------------------------------------------------------------------
__global__ __launch_bounds__(256) void head_fused_kernel(
    const float* __restrict__ skip39, const float* __restrict__ e1,
    const float* __restrict__ b1, const float* __restrict__ e2,
    const float* __restrict__ b2, float* __restrict__ out)
{
    __shared__ __align__(16) float zt[32 * 32];
    __shared__ __align__(16) float s_sm[256 * 32];

    const int b  = blockIdx.y;
    const int j0 = blockIdx.x * 32;
    const int tid = threadIdx.x;
    const int p = tid & 31, g = tid >> 5;

    const float* zsrc = g_bufA + (size_t)b * 32 * W + 4096 + j0;
#pragma unroll
    for (int it = 0; it < 4; it++) {
        int r = it * 8 + g;
        zt[r * 32 + p] = zsrc[(size_t)r * W + p];
    }
    __syncthreads();

    float zr[32];
#pragma unroll
    for (int r = 0; r < 32; r++) zr[r] = zt[r * 32 + p];

#pragma unroll 4
    for (int cl = 0; cl < 32; cl++) {
        int c = g * 32 + cl;
        const float4* skv = (const float4*)(skip39 + c * 32);
        float a0 = 0.f, a1 = 0.f;
#pragma unroll
        for (int r4 = 0; r4 < 8; r4++) {
            float4 w = __ldg(&skv[r4]);
            a0 = fmaf(w.x, zr[4 * r4 + 0], a0);
            a1 = fmaf(w.y, zr[4 * r4 + 1], a1);
            a0 = fmaf(w.z, zr[4 * r4 + 2], a0);
            a1 = fmaf(w.w, zr[4 * r4 + 3], a1);
        }
        s_sm[c * 32 + p] = fmaxf(a0 + a1, 0.f);
    }
    __syncthreads();

    unsigned long long accp[16];
#pragma unroll
    for (int i = 0; i < 16; i++) accp[i] = 0ull;

    const float4* e1row = (const float4*)(e1 + tid * 256);
    for (int s4i = 0; s4i < 64; s4i++) {
        float4 w4 = __ldg(e1row + s4i);
        const float ws[4] = {w4.x, w4.y, w4.z, w4.w};
#pragma unroll
        for (int ss = 0; ss < 4; ss++) {
            unsigned long long wd = pack2(ws[ss], ws[ss]);
            const ulonglong2* sv = (const ulonglong2*)(s_sm + (s4i * 4 + ss) * 32);
#pragma unroll
            for (int q = 0; q < 8; q++) {
                ulonglong2 sx = sv[q];
                accp[2 * q]     = ffma2(wd, sx.x, accp[2 * q]);
                accp[2 * q + 1] = ffma2(wd, sx.y, accp[2 * q + 1]);
            }
        }
    }

    float h[32];
    {
        float bias1 = b1[tid];
#pragma unroll
        for (int q = 0; q < 8; q++) {
            float2 u = unpack2(accp[2 * q]);
            float2 v = unpack2(accp[2 * q + 1]);
            h[4 * q + 0] = fmaxf(u.x + bias1, 0.f);
            h[4 * q + 1] = fmaxf(u.y + bias1, 0.f);
            h[4 * q + 2] = fmaxf(v.x + bias1, 0.f);
            h[4 * q + 3] = fmaxf(v.y + bias1, 0.f);
        }
    }

    __syncthreads();
    {
        float4* dst = (float4*)(s_sm + tid * 32);
#pragma unroll
        for (int q = 0; q < 8; q++)
            dst[q] = make_float4(h[4 * q], h[4 * q + 1], h[4 * q + 2], h[4 * q + 3]);
    }
    __syncthreads();

#pragma unroll
    for (int i = 0; i < 16; i++) accp[i] = 0ull;

    const float4* e2row = (const float4*)(e2 + tid * 256);
    for (int s4i = 0; s4i < 64; s4i++) {
        float4 w4 = __ldg(e2row + s4i);
        const float ws[4] = {w4.x, w4.y, w4.z, w4.w};
#pragma unroll
        for (int ss = 0; ss < 4; ss++) {
            unsigned long long wd = pack2(ws[ss], ws[ss]);
            const ulonglong2* hv = (const ulonglong2*)(s_sm + (s4i * 4 + ss) * 32);
#pragma unroll
            for (int q = 0; q < 8; q++) {
                ulonglong2 hx = hv[q];
                accp[2 * q]     = ffma2(wd, hx.x, accp[2 * q]);
                accp[2 * q + 1] = ffma2(wd, hx.y, accp[2 * q + 1]);
            }
        }
    }

    float bias2 = b2[tid];
    float* ob = out + ((size_t)b * 4096 + j0) * 256 + tid;
#pragma unroll
    for (int q = 0; q < 8; q++) {
        float2 u = unpack2(accp[2 * q]);
        float2 v = unpack2(accp[2 * q + 1]);
        ob[(size_t)(4 * q + 0) * 256] = u.x + bias2;
        ob[(size_t)(4 * q + 1) * 256] = u.y + bias2;
        ob[(size_t)(4 * q + 2) * 256] = v.x + bias2;
        ob[(size_t)(4 * q + 3) * 256] = v.y + bias2;
    }
}

// ---------------------------------------------------------------------------

extern "C" void kernel_launch(void* const* d_in, const int* in_sizes, int n_in,
                              void* d_out, int out_size)
{
    (void)in_sizes; (void)n_in; (void)out_size;
    const float* x_input    = (const float*)d_in[0];
    const float* start_w    = (const float*)d_in[1];
    const float* filter_w   = (const float*)d_in[2];
    const float* gate_w     = (const float*)d_in[3];
    const float* residual_w = (const float*)d_in[4];
    const float* skip_w     = (const float*)d_in[5];
    const float* e1         = (const float*)d_in[6];
    const float* b1         = (const float*)d_in[7];
    const float* e2         = (const float*)d_in[8];
    const float* b2         = (const float*)d_in[9];
    float* out = (float*)d_out;

    // dilations: 4 blocks of 1,2,4,...,512
    int ds[40];
    {
        int idx = 0;
        for (int blk = 0; blk < 4; blk++) {
            int nd = 1;
            for (int l = 0; l < 10; l++) { ds[idx++] = nd; nd *= 2; }
        }
    }
    // S[i] = 4096 - sum_{j>i} ds[j]  (valid output start for layer i)
    int S[40];
    {
        int suf = 0;
        for (int i = 39; i >= 0; i--) { S[i] = 4096 - suf; suf += ds[i]; }
    }

    start_kernel<<<dim3(32, 8), 128>>>(x_input, start_w);

    for (int i = 0; i < 40; i++) {
        int tstart = S[i];
        int n = W - tstart;
        int gx = (n + 127) / 128;
        layer_kernel<<<dim3(gx, 8), 128>>>(
            filter_w + (size_t)i * 2048, gate_w + (size_t)i * 2048,
            residual_w + (size_t)i * 1024,
            ds[i], tstart, i & 1, (i == 39) ? 1 : 0);
    }

    head_fused_kernel<<<dim3(128, 8), 256>>>(
        skip_w + (size_t)39 * 256 * 32, e1, b1, e2, b2, out);
}

// round 14
// speedup vs baseline: 1.4794x; 1.4794x over previous
#include <cuda_runtime.h>

#define W 8192

static __device__ __align__(16) float g_bufA[8 * 32 * W];
static __device__ __align__(16) float g_bufB[8 * 32 * W];

// ---- packed f32x2 helpers (sm_103a FFMA2 path) ----------------------------
__device__ __forceinline__ unsigned long long ffma2(
    unsigned long long a, unsigned long long b, unsigned long long c)
{
    unsigned long long d;
    asm("fma.rn.f32x2 %0, %1, %2, %3;" : "=l"(d) : "l"(a), "l"(b), "l"(c));
    return d;
}
__device__ __forceinline__ unsigned long long pack2(float lo, float hi)
{
    unsigned long long r;
    asm("mov.b64 %0, {%1, %2};" : "=l"(r) : "f"(lo), "f"(hi));
    return r;
}
__device__ __forceinline__ float2 unpack2(unsigned long long v)
{
    float2 r;
    asm("mov.b64 {%0, %1}, %2;" : "=f"(r.x), "=f"(r.y) : "l"(v));
    return r;
}
__device__ __forceinline__ float tanh_approx(float x)
{
    float y;
    asm("tanh.approx.f32 %0, %1;" : "=f"(y) : "f"(x));
    return y;
}

// ---------------------------------------------------------------------------
// Start conv: bufA[b,c,ti] = sum_k start_w[c,k] * x_input[b,k,8192+ti]
// ---------------------------------------------------------------------------
__global__ __launch_bounds__(128) void start_kernel(
    const float* __restrict__ x_input, const float* __restrict__ start_w)
{
    __shared__ __align__(16) float wsm[32 * 256];  // [c][k]
    const int b = blockIdx.y;
    for (int i = threadIdx.x; i < 32 * 256; i += 128) wsm[i] = start_w[i];
    __syncthreads();

    const int ti = (blockIdx.x * 128 + threadIdx.x) * 2;
    const float* xb = x_input + (size_t)b * 256 * 16384 + 8192 + ti;

    float2 acc[32];
#pragma unroll
    for (int c = 0; c < 32; c++) acc[c] = make_float2(0.f, 0.f);

    const float4* wv = (const float4*)wsm;
#pragma unroll 4
    for (int k4 = 0; k4 < 64; k4++) {
        float2 x0 = *(const float2*)(xb + (size_t)(k4 * 4 + 0) * 16384);
        float2 x1 = *(const float2*)(xb + (size_t)(k4 * 4 + 1) * 16384);
        float2 x2 = *(const float2*)(xb + (size_t)(k4 * 4 + 2) * 16384);
        float2 x3 = *(const float2*)(xb + (size_t)(k4 * 4 + 3) * 16384);
#pragma unroll
        for (int c = 0; c < 32; c++) {
            float4 w = wv[c * 64 + k4];
            acc[c].x = fmaf(w.x, x0.x, acc[c].x);
            acc[c].y = fmaf(w.x, x0.y, acc[c].y);
            acc[c].x = fmaf(w.y, x1.x, acc[c].x);
            acc[c].y = fmaf(w.y, x1.y, acc[c].y);
            acc[c].x = fmaf(w.z, x2.x, acc[c].x);
            acc[c].y = fmaf(w.z, x2.y, acc[c].y);
            acc[c].x = fmaf(w.w, x3.x, acc[c].x);
            acc[c].y = fmaf(w.w, x3.y, acc[c].y);
        }
    }
#pragma unroll
    for (int c = 0; c < 32; c++)
        *(float2*)(&g_bufA[((size_t)b * 32 + c) * W + ti]) = acc[c];
}

// ---------------------------------------------------------------------------
// WaveNet layer: 2 positions/thread (stride 64) x half-channel split,
// weights in SMEM (broadcast LDS), gated exchange in 2 chunks of 8 channels.
// Block = 128 threads covers 128 positions.
// Dynamic smem 56KB: sF 8K | sG 8K | sRd 8K (dup (w,w) ull) | exch 16K | zsh 16K
// ---------------------------------------------------------------------------
__global__ __launch_bounds__(128, 4) void layer_kernel(
    const float* __restrict__ filt, const float* __restrict__ gate,
    const float* __restrict__ resid, int d, int tstart, int dir, int last)
{
    extern __shared__ __align__(16) float smem[];
    float* sF   = smem;                 // 2048 floats
    float* sG   = smem + 2048;          // 2048 floats
    unsigned long long* sRd = (unsigned long long*)(smem + 4096);  // 1024 ull
    float* exch = smem + 6144;          // 4096 floats: [slot16][2][128]
    unsigned long long* zull = (unsigned long long*)(smem + 10240); // 2048 ull

    {
        const float4* f4 = (const float4*)filt;
        const float4* g4 = (const float4*)gate;
        float4* sF4 = (float4*)sF;
        float4* sG4 = (float4*)sG;
        for (int i = threadIdx.x; i < 512; i += 128) { sF4[i] = f4[i]; sG4[i] = g4[i]; }
        for (int i = threadIdx.x; i < 1024; i += 128) {
            float v = resid[i];
            sRd[i] = pack2(v, v);
        }
    }
    __syncthreads();

    const float* xin  = dir ? g_bufB : g_bufA;
    float*       xout = dir ? g_bufA : g_bufB;

    const int tp = threadIdx.x & 63;
    const int h  = threadIdx.x >> 6;
    const int hc = h << 4;

    const int base = tstart + blockIdx.x * 128;
    const int ti0 = base + tp;
    const int ti1 = ti0 + 64;
    const bool v0 = (ti0 < W), v1 = (ti1 < W);
    const int t0 = v0 ? ti0 : (W - 1);
    const int t1 = v1 ? ti1 : (W - 1);

    const float* xb = xin + (size_t)blockIdx.y * 32 * W;
    float*       ob = xout + (size_t)blockIdx.y * 32 * W;

    // (prev,cur) packed for this half's 16 in-channels, both positions
    unsigned long long cp0[16], cp1[16];
#pragma unroll
    for (int r = 0; r < 16; r++) {
        const float* xr = xb + (hc + r) * W;
        cp0[r] = pack2(xr[t0 - d], xr[t0]);
        cp1[r] = pack2(xr[t1 - d], xr[t1]);
    }

    // ---- gated conv in 2 chunks of 8 output channels per half ----
#pragma unroll
    for (int k = 0; k < 2; k++) {
        // phase A: partials for the OTHER half's chunk -> exch
        const int ocA = (16 - hc) + k * 8;   // other half's channel base
#pragma unroll
        for (int cl = 0; cl < 8; cl++) {
            const int c = ocA + cl;
            const ulonglong2* fw = (const ulonglong2*)(sF + c * 64 + hc * 2);
            const ulonglong2* gw = (const ulonglong2*)(sG + c * 64 + hc * 2);
            unsigned long long fa0 = 0, fb0 = 0, fa1 = 0, fb1 = 0;
            unsigned long long ga0 = 0, gb0 = 0, ga1 = 0, gb1 = 0;
#pragma unroll
            for (int j = 0; j < 8; j++) {
                ulonglong2 wf = fw[j];
                ulonglong2 wg = gw[j];
                fa0 = ffma2(wf.x, cp0[2 * j],     fa0);
                fb0 = ffma2(wf.y, cp0[2 * j + 1], fb0);
                fa1 = ffma2(wf.x, cp1[2 * j],     fa1);
                fb1 = ffma2(wf.y, cp1[2 * j + 1], fb1);
                ga0 = ffma2(wg.x, cp0[2 * j],     ga0);
                gb0 = ffma2(wg.y, cp0[2 * j + 1], gb0);
                ga1 = ffma2(wg.x, cp1[2 * j],     ga1);
                gb1 = ffma2(wg.y, cp1[2 * j + 1], gb1);
            }
            // writer h stores into slots [8*(1-h) + cl]
            const int slot = (8 - 8 * h) + cl;
            float2 u, v;
            u = unpack2(fa0); v = unpack2(fb0);
            exch[slot * 256 + tp]       = (u.x + u.y) + (v.x + v.y);
            u = unpack2(fa1); v = unpack2(fb1);
            exch[slot * 256 + tp + 64]  = (u.x + u.y) + (v.x + v.y);
            u = unpack2(ga0); v = unpack2(gb0);
            exch[slot * 256 + 128 + tp]      = (u.x + u.y) + (v.x + v.y);
            u = unpack2(ga1); v = unpack2(gb1);
            exch[slot * 256 + 128 + tp + 64] = (u.x + u.y) + (v.x + v.y);
        }
        __syncthreads();

        // phase B: OWN chunk: partial + exch, activate, store z (or gmem if last)
#pragma unroll
        for (int cl = 0; cl < 8; cl++) {
            const int c = hc + k * 8 + cl;
            const ulonglong2* fw = (const ulonglong2*)(sF + c * 64 + hc * 2);
            const ulonglong2* gw = (const ulonglong2*)(sG + c * 64 + hc * 2);
            unsigned long long fa0 = 0, fb0 = 0, fa1 = 0, fb1 = 0;
            unsigned long long ga0 = 0, gb0 = 0, ga1 = 0, gb1 = 0;
#pragma unroll
            for (int j = 0; j < 8; j++) {
                ulonglong2 wf = fw[j];
                ulonglong2 wg = gw[j];
                fa0 = ffma2(wf.x, cp0[2 * j],     fa0);
                fb0 = ffma2(wf.y, cp0[2 * j + 1], fb0);
                fa1 = ffma2(wf.x, cp1[2 * j],     fa1);
                fb1 = ffma2(wf.y, cp1[2 * j + 1], fb1);
                ga0 = ffma2(wg.x, cp0[2 * j],     ga0);
                gb0 = ffma2(wg.y, cp0[2 * j + 1], gb0);
                ga1 = ffma2(wg.x, cp1[2 * j],     ga1);
                gb1 = ffma2(wg.y, cp1[2 * j + 1], gb1);
            }
            const int slot = 8 * h + cl;     // written by the other half
            float2 u, v;
            u = unpack2(fa0); v = unpack2(fb0);
            float pa0 = (u.x + u.y) + (v.x + v.y) + exch[slot * 256 + tp];
            u = unpack2(fa1); v = unpack2(fb1);
            float pa1 = (u.x + u.y) + (v.x + v.y) + exch[slot * 256 + tp + 64];
            u = unpack2(ga0); v = unpack2(gb0);
            float pg0 = (u.x + u.y) + (v.x + v.y) + exch[slot * 256 + 128 + tp];
            u = unpack2(ga1); v = unpack2(gb1);
            float pg1 = (u.x + u.y) + (v.x + v.y) + exch[slot * 256 + 128 + tp + 64];

            float z0 = tanh_approx(pa0) * fmaf(0.5f, tanh_approx(0.5f * pg0), 0.5f);
            float z1 = tanh_approx(pa1) * fmaf(0.5f, tanh_approx(0.5f * pg1), 0.5f);

            if (last) {
                if (v0) ob[c * W + ti0] = z0;
                if (v1) ob[c * W + ti1] = z1;
            } else {
                zull[c * 64 + tp] = pack2(z0, z1);
            }
        }
        __syncthreads();
    }
    if (last) return;   // uniform

    // ---- residual conv: OWN 16 out channels, pos-packed accumulators ----
    unsigned long long racc[16];
#pragma unroll
    for (int cl = 0; cl < 16; cl++)
        racc[cl] = pack2(unpack2(cp0[cl]).y, unpack2(cp1[cl]).y);

#pragma unroll
    for (int ch = 0; ch < 4; ch++) {      // z channels in chunks of 8
        unsigned long long zr[8];
#pragma unroll
        for (int r = 0; r < 8; r++) zr[r] = zull[(ch * 8 + r) * 64 + tp];
#pragma unroll
        for (int cl = 0; cl < 16; cl++) {
            const ulonglong2* rw =
                (const ulonglong2*)(sRd + (hc + cl) * 32 + ch * 8);
#pragma unroll
            for (int q = 0; q < 4; q++) {
                ulonglong2 w = rw[q];
                racc[cl] = ffma2(w.x, zr[2 * q],     racc[cl]);
                racc[cl] = ffma2(w.y, zr[2 * q + 1], racc[cl]);
            }
        }
    }

#pragma unroll
    for (int cl = 0; cl < 16; cl++) {
        const int c = hc + cl;
        float2 o = unpack2(racc[cl]);
        if (v0) ob[c * W + ti0] = o.x;
        if (v1) ob[c * W + ti1] = o.y;
    }
}

// ---------------------------------------------------------------------------
// Fused head: out = e2 @ relu(e1 @ relu(skip39 @ z) + b1) + b2
// (verified R11 version, unchanged)
// ---------------------------------------------------------------------------
__global__ __launch_bounds__(256) void head_fused_kernel(
    const float* __restrict__ skip39, const float* __restrict__ e1,
    const float* __restrict__ b1, const float* __restrict__ e2,
    const float* __restrict__ b2, float* __restrict__ out)
{
    __shared__ __align__(16) float zt[32 * 32];
    __shared__ __align__(16) float s_sm[256 * 32];

    const int b  = blockIdx.y;
    const int j0 = blockIdx.x * 32;
    const int tid = threadIdx.x;
    const int p = tid & 31, g = tid >> 5;

    const float* zsrc = g_bufA + (size_t)b * 32 * W + 4096 + j0;
#pragma unroll
    for (int it = 0; it < 4; it++) {
        int r = it * 8 + g;
        zt[r * 32 + p] = zsrc[(size_t)r * W + p];
    }
    __syncthreads();

    float zr[32];
#pragma unroll
    for (int r = 0; r < 32; r++) zr[r] = zt[r * 32 + p];

#pragma unroll 4
    for (int cl = 0; cl < 32; cl++) {
        int c = g * 32 + cl;
        const float4* skv = (const float4*)(skip39 + c * 32);
        float a0 = 0.f, a1 = 0.f;
#pragma unroll
        for (int r4 = 0; r4 < 8; r4++) {
            float4 w = __ldg(&skv[r4]);
            a0 = fmaf(w.x, zr[4 * r4 + 0], a0);
            a1 = fmaf(w.y, zr[4 * r4 + 1], a1);
            a0 = fmaf(w.z, zr[4 * r4 + 2], a0);
            a1 = fmaf(w.w, zr[4 * r4 + 3], a1);
        }
        s_sm[c * 32 + p] = fmaxf(a0 + a1, 0.f);
    }
    __syncthreads();

    unsigned long long accp[16];
#pragma unroll
    for (int i = 0; i < 16; i++) accp[i] = 0ull;

    const float4* e1row = (const float4*)(e1 + tid * 256);
    for (int s4i = 0; s4i < 64; s4i++) {
        float4 w4 = __ldg(e1row + s4i);
        const float ws[4] = {w4.x, w4.y, w4.z, w4.w};
#pragma unroll
        for (int ss = 0; ss < 4; ss++) {
            unsigned long long wd = pack2(ws[ss], ws[ss]);
            const ulonglong2* sv = (const ulonglong2*)(s_sm + (s4i * 4 + ss) * 32);
#pragma unroll
            for (int q = 0; q < 8; q++) {
                ulonglong2 sx = sv[q];
                accp[2 * q]     = ffma2(wd, sx.x, accp[2 * q]);
                accp[2 * q + 1] = ffma2(wd, sx.y, accp[2 * q + 1]);
            }
        }
    }

    float h[32];
    {
        float bias1 = b1[tid];
#pragma unroll
        for (int q = 0; q < 8; q++) {
            float2 u = unpack2(accp[2 * q]);
            float2 v = unpack2(accp[2 * q + 1]);
            h[4 * q + 0] = fmaxf(u.x + bias1, 0.f);
            h[4 * q + 1] = fmaxf(u.y + bias1, 0.f);
            h[4 * q + 2] = fmaxf(v.x + bias1, 0.f);
            h[4 * q + 3] = fmaxf(v.y + bias1, 0.f);
        }
    }

    __syncthreads();
    {
        float4* dst = (float4*)(s_sm + tid * 32);
#pragma unroll
        for (int q = 0; q < 8; q++)
            dst[q] = make_float4(h[4 * q], h[4 * q + 1], h[4 * q + 2], h[4 * q + 3]);
    }
    __syncthreads();

#pragma unroll
    for (int i = 0; i < 16; i++) accp[i] = 0ull;

    const float4* e2row = (const float4*)(e2 + tid * 256);
    for (int s4i = 0; s4i < 64; s4i++) {
        float4 w4 = __ldg(e2row + s4i);
        const float ws[4] = {w4.x, w4.y, w4.z, w4.w};
#pragma unroll
        for (int ss = 0; ss < 4; ss++) {
            unsigned long long wd = pack2(ws[ss], ws[ss]);
            const ulonglong2* hv = (const ulonglong2*)(s_sm + (s4i * 4 + ss) * 32);
#pragma unroll
            for (int q = 0; q < 8; q++) {
                ulonglong2 hx = hv[q];
                accp[2 * q]     = ffma2(wd, hx.x, accp[2 * q]);
                accp[2 * q + 1] = ffma2(wd, hx.y, accp[2 * q + 1]);
            }
        }
    }

    float bias2 = b2[tid];
    float* ob = out + ((size_t)b * 4096 + j0) * 256 + tid;
#pragma unroll
    for (int q = 0; q < 8; q++) {
        float2 u = unpack2(accp[2 * q]);
        float2 v = unpack2(accp[2 * q + 1]);
        ob[(size_t)(4 * q + 0) * 256] = u.x + bias2;
        ob[(size_t)(4 * q + 1) * 256] = u.y + bias2;
        ob[(size_t)(4 * q + 2) * 256] = v.x + bias2;
        ob[(size_t)(4 * q + 3) * 256] = v.y + bias2;
    }
}

// ---------------------------------------------------------------------------

extern "C" void kernel_launch(void* const* d_in, const int* in_sizes, int n_in,
                              void* d_out, int out_size)
{
    (void)in_sizes; (void)n_in; (void)out_size;
    const float* x_input    = (const float*)d_in[0];
    const float* start_w    = (const float*)d_in[1];
    const float* filter_w   = (const float*)d_in[2];
    const float* gate_w     = (const float*)d_in[3];
    const float* residual_w = (const float*)d_in[4];
    const float* skip_w     = (const float*)d_in[5];
    const float* e1         = (const float*)d_in[6];
    const float* b1         = (const float*)d_in[7];
    const float* e2         = (const float*)d_in[8];
    const float* b2         = (const float*)d_in[9];
    float* out = (float*)d_out;

    const int LAYER_SMEM = 14336 * 4;   // 56 KB dynamic
    static int configured = 0;
    if (!configured) {
        cudaFuncSetAttribute(layer_kernel,
                             cudaFuncAttributeMaxDynamicSharedMemorySize,
                             LAYER_SMEM);
        configured = 1;
    }

    // dilations: 4 blocks of 1,2,4,...,512
    int ds[40];
    {
        int idx = 0;
        for (int blk = 0; blk < 4; blk++) {
            int nd = 1;
            for (int l = 0; l < 10; l++) { ds[idx++] = nd; nd *= 2; }
        }
    }
    // S[i] = 4096 - sum_{j>i} ds[j]  (valid output start for layer i)
    int S[40];
    {
        int suf = 0;
        for (int i = 39; i >= 0; i--) { S[i] = 4096 - suf; suf += ds[i]; }
    }

    start_kernel<<<dim3(32, 8), 128>>>(x_input, start_w);

    for (int i = 0; i < 40; i++) {
        int tstart = S[i];
        int n = W - tstart;
        int gx = (n + 127) / 128;
        layer_kernel<<<dim3(gx, 8), 128, LAYER_SMEM>>>(
            filter_w + (size_t)i * 2048, gate_w + (size_t)i * 2048,
            residual_w + (size_t)i * 1024,
            ds[i], tstart, i & 1, (i == 39) ? 1 : 0);
    }

    head_fused_kernel<<<dim3(128, 8), 256>>>(
        skip_w + (size_t)39 * 256 * 32, e1, b1, e2, b2, out);
}